// round 7
// baseline (speedup 1.0000x reference)
#include <cuda_runtime.h>
#include <cstdint>

// ---------------------------------------------------------------------------
// MultiScaleRoIAlign (torchvision, aligned=False, SR=2) — single kernel.
// grid=(512 rois, 4 slices of 64 ch), block=256.
// 16 chunks of 4 channels; cp.async staging into a 3-buffer ring with
// prefetch distance 2 (group ck committed 2 iterations before its wait, so
// ~2 chunks of compute+issue hide the DRAM round trip). Compute: 196 threads,
// one (channel,bin) output each, bilinear params precomputed in registers.
// Window bound: hr * rs2 <= 768 float2 per channel (level mapper: s_scaled<28).
// ---------------------------------------------------------------------------

#define WS2 768   // float2 slots per channel window

__device__ __forceinline__ void cp_async8(uint32_t dst, const void* src, bool p)
{
    if (p) asm volatile("cp.async.ca.shared.global [%0], [%1], 8;"
                        :: "r"(dst), "l"(src) : "memory");
}
__device__ __forceinline__ void cp_async4(uint32_t dst, const void* src, bool p)
{
    if (p) asm volatile("cp.async.ca.shared.global [%0], [%1], 4;"
                        :: "r"(dst), "l"(src) : "memory");
}
#define CP_COMMIT()  asm volatile("cp.async.commit_group;" ::: "memory")
#define CP_WAIT(N)   asm volatile("cp.async.wait_group %0;" :: "n"(N) : "memory")

__global__ void __launch_bounds__(256, 3)
msroi_kernel(const float* __restrict__ f0, const float* __restrict__ f1,
             const float* __restrict__ f2, const float* __restrict__ f3,
             const float* __restrict__ boxes, float* __restrict__ out)
{
    __shared__ float2 win[3][4][WS2];
    __shared__ float s_hy[14], s_ly[14], s_hx[14], s_lx[14];
    __shared__ int   s_yl[14], s_yh[14], s_xl[14], s_xh[14];

    const int tid = threadIdx.x;
    const int n = blockIdx.x;
    const int b = n >> 8;

    float4 bx = __ldg(reinterpret_cast<const float4*>(boxes) + n);

    // LevelMapper: floor(4 + log2(sqrt(w*h)/224) + 1e-6), clip [2,5], -2
    float s = sqrtf((bx.z - bx.x) * (bx.w - bx.y));
    int lvl = (int)floorf(4.0f + log2f(s * (1.0f / 224.0f)) + 1e-6f);
    lvl = min(max(lvl, 2), 5) - 2;

    int H; float sc; const float* base;
    switch (lvl) {
        case 0:  H = 200; sc = 0.25f;    base = f0; break;
        case 1:  H = 100; sc = 0.125f;   base = f1; break;
        case 2:  H = 50;  sc = 0.0625f;  base = f2; break;
        default: H = 25;  sc = 0.03125f; base = f3; break;
    }
    const int HH = H * H;
    base += (size_t)b * 256 * HH;

    float x1s = bx.x * sc, y1s = bx.y * sc;
    float x2s = bx.z * sc, y2s = bx.w * sc;
    float binw = fmaxf(x2s - x1s, 1.0f) * (1.0f / 7.0f);
    float binh = fmaxf(y2s - y1s, 1.0f) * (1.0f / 7.0f);
    float fH = (float)H;

    // window bounds
    float ymin = y1s + 0.25f * binh, ymax = y1s + 6.75f * binh;
    float xmin = x1s + 0.25f * binw, xmax = x1s + 6.75f * binw;
    int y0  = min((int)fmaxf(ymin, 0.0f), H - 1);
    int x0  = min((int)fmaxf(xmin, 0.0f), H - 1);
    int y1m = min((int)fmaxf(fminf(ymax, fH - 1.0f), 0.0f) + 1, H - 1);
    int x1m = min((int)fmaxf(fminf(xmax, fH - 1.0f), 0.0f) + 1, H - 1);
    int hr  = y1m - y0 + 1;
    int x0d = x0 & ~1;                         // float2-aligned window start
    int wc2 = (x1m >> 1) - (x0d >> 1) + 1;     // float2 per row
    int rs2 = wc2 | 1;                         // odd float2 row stride
    const int rsF = rs2 * 2;                   // float row stride

    // per-sample bilinear params (14 y, 14 x)
    if (tid < 28) {
        bool isY = tid < 14;
        int j = isY ? tid : tid - 14;
        float o = (float)(j >> 1) + 0.25f + 0.5f * (float)(j & 1);
        float v = isY ? (y1s + o * binh) : (x1s + o * binw);
        bool valid = (v > -1.0f) && (v < fH);
        float vc = fmaxf(v, 0.0f);
        int lo = min((int)vc, H - 1);
        int hi = min(lo + 1, H - 1);
        float l = (lo >= H - 1) ? 0.0f : (vc - (float)lo);
        float h = 1.0f - l;
        if (!valid) { l = 0.0f; h = 0.0f; lo = isY ? y0 : x0d; hi = lo; }
        if (isY) { s_yl[j] = lo - y0;  s_yh[j] = hi - y0;  s_ly[j] = l; s_hy[j] = h; }
        else     { s_xl[j] = lo - x0d; s_xh[j] = hi - x0d; s_lx[j] = l; s_hx[j] = h; }
    }
    __syncthreads();

    // ---- per-thread compute params in registers (tid < 196) ----
    int cidx = 0, r0a = 0, r1a = 0, r0b = 0, r1b = 0, xl0 = 0, xh0 = 0, xl1 = 0, xh1 = 0;
    float hy0 = 0, ly0 = 0, hy1 = 0, ly1 = 0, hx0 = 0, lx0 = 0, hx1 = 0, lx1 = 0;
    if (tid < 196) {
        cidx = tid / 49;
        int bin = tid - cidx * 49;
        int oy = bin / 7, ox = bin - oy * 7;
        int j0 = oy * 2, j1 = j0 + 1, k0 = ox * 2, k1 = k0 + 1;
        r0a = s_yl[j0] * rsF; r1a = s_yh[j0] * rsF;
        r0b = s_yl[j1] * rsF; r1b = s_yh[j1] * rsF;
        xl0 = s_xl[k0]; xh0 = s_xh[k0]; xl1 = s_xl[k1]; xh1 = s_xh[k1];
        hy0 = s_hy[j0]; ly0 = s_ly[j0]; hy1 = s_hy[j1]; ly1 = s_ly[j1];
        hx0 = s_hx[k0]; lx0 = s_lx[k0]; hx1 = s_hx[k1]; lx1 = s_lx[k1];
    }
    float* outp = out + (size_t)n * 12544 + blockIdx.y * (64 * 49) + tid;

    // ---- staging lane geometry ----
    const int warp = tid >> 5, lane = tid & 31;
    const int cw = warp & 3, half = warp >> 2;   // 2 warps per channel
    const int cbase = blockIdx.y * 64;
    const bool h25 = (H == 25);
    const int wide = h25 ? (wc2 * 2) : wc2;      // elements per row (f32 / f2)
    int wp2 = 1;
    while (wp2 < wide && wp2 < 32) wp2 <<= 1;
    const int shift = __popc(wp2 - 1);
    const int rpw = 32 >> shift;                 // rows per warp step
    const int lxe = lane & (wp2 - 1);
    const int lr0 = lane >> shift;
    const int H2 = H >> 1;
    const int xlim = x1m - x0d;                  // scalar-path x predicate

    // stage chunk ck's 4 channels into buffer bf via cp.async (no reg dep)
    auto stage = [&](int bf, int ck) {
        const int cglob = cbase + ck * 4 + cw;
        uint32_t wb = (uint32_t)__cvta_generic_to_shared(&win[bf][cw][0]);
        if (!h25) {
            const float2* src = reinterpret_cast<const float2*>(base)
                              + (size_t)cglob * (HH >> 1) + y0 * H2 + (x0d >> 1);
            for (int cx0 = 0; cx0 < wc2; cx0 += wp2) {
                int xx = cx0 + lxe;
                bool inx = xx < wc2;
                for (int rb0 = half * 2 * rpw; rb0 < hr; rb0 += 4 * rpw) {
                    int ra = rb0 + lr0, rb = ra + rpw;
                    cp_async8(wb + (uint32_t)(ra * rs2 + xx) * 8u,
                              src + ra * H2 + xx, inx && ra < hr);
                    cp_async8(wb + (uint32_t)(rb * rs2 + xx) * 8u,
                              src + rb * H2 + xx, inx && rb < hr);
                }
            }
        } else {
            const float* src = base + (size_t)cglob * HH + y0 * H + x0d;
            for (int cx0 = 0; cx0 < wide; cx0 += wp2) {
                int xx = cx0 + lxe;
                bool inx = xx <= xlim;
                for (int rb0 = half * 2 * rpw; rb0 < hr; rb0 += 4 * rpw) {
                    int ra = rb0 + lr0, rb = ra + rpw;
                    cp_async4(wb + (uint32_t)(ra * rsF + xx) * 4u,
                              src + ra * H + xx, inx && ra < hr);
                    cp_async4(wb + (uint32_t)(rb * rsF + xx) * 4u,
                              src + rb * H + xx, inx && rb < hr);
                }
            }
        }
    };

    // prologue: two chunks in flight
    stage(0, 0); CP_COMMIT();
    stage(1, 1); CP_COMMIT();

    #pragma unroll 1
    for (int ck = 0; ck < 16; ck++) {
        int bf = ck % 3;
        if (ck + 2 < 16) {
            stage((ck + 2) % 3, ck + 2);   // buf (ck-1)%3: freed by prev barrier
            CP_COMMIT();
            CP_WAIT(2);                    // group ck complete
        } else if (ck + 1 < 16) {
            CP_WAIT(1);
        } else {
            CP_WAIT(0);
        }
        __syncthreads();                   // all threads' groups for ck landed

        if (tid < 196) {
            const float* W = reinterpret_cast<const float*>(win[bf][cidx]);
            float acc =
                  hy0 * (hx0 * W[r0a + xl0] + lx0 * W[r0a + xh0])
                + ly0 * (hx0 * W[r1a + xl0] + lx0 * W[r1a + xh0])
                + hy0 * (hx1 * W[r0a + xl1] + lx1 * W[r0a + xh1])
                + ly0 * (hx1 * W[r1a + xl1] + lx1 * W[r1a + xh1])
                + hy1 * (hx0 * W[r0b + xl0] + lx0 * W[r0b + xh0])
                + ly1 * (hx0 * W[r1b + xl0] + lx0 * W[r1b + xh0])
                + hy1 * (hx1 * W[r0b + xl1] + lx1 * W[r0b + xh1])
                + ly1 * (hx1 * W[r1b + xl1] + lx1 * W[r1b + xh1]);
            outp[ck * 196] = acc * 0.25f;
        }
        __syncthreads();                   // done reading bf before restage
    }
}

extern "C" void kernel_launch(void* const* d_in, const int* in_sizes, int n_in,
                              void* d_out, int out_size)
{
    const float* f0 = (const float*)d_in[0];
    const float* f1 = (const float*)d_in[1];
    const float* f2 = (const float*)d_in[2];
    const float* f3 = (const float*)d_in[3];
    const float* boxes = (const float*)d_in[4];
    float* out = (float*)d_out;

    msroi_kernel<<<dim3(512, 4), 256>>>(f0, f1, f2, f3, boxes, out);
}

// round 8
// speedup vs baseline: 1.3034x; 1.3034x over previous
#include <cuda_runtime.h>
#include <cstdint>

// ---------------------------------------------------------------------------
// MultiScaleRoIAlign (torchvision, aligned=False, SR=2) — warp-autonomous.
// grid=(512 rois, 4 slices of 64 ch), block=256 (8 warps).
// Warp w owns channels {cbase + k*8 + w}; it cp.async-stages channel k+2's
// window into its private 3-buffer smem ring while computing channel k.
// No block barriers in the main loop (only __syncwarp). Bilinear params are
// per-bin and cached in registers (bin=lane and bin=32+lane for lane<17).
// Windows with hr*rs2 > 512 float2 (rare extreme-aspect ROIs) take a direct
// global-memory path (uniform per block).
// ---------------------------------------------------------------------------

#define WS2 512   // float2 slots per window buffer

__device__ __forceinline__ void cp_async8(uint32_t dst, const void* src, bool p)
{
    if (p) asm volatile("cp.async.ca.shared.global [%0], [%1], 8;"
                        :: "r"(dst), "l"(src) : "memory");
}
__device__ __forceinline__ void cp_async4(uint32_t dst, const void* src, bool p)
{
    if (p) asm volatile("cp.async.ca.shared.global [%0], [%1], 4;"
                        :: "r"(dst), "l"(src) : "memory");
}
#define CP_COMMIT()  asm volatile("cp.async.commit_group;" ::: "memory")
#define CP_WAIT(N)   asm volatile("cp.async.wait_group %0;" :: "n"(N) : "memory")

__global__ void __launch_bounds__(256, 2)
msroi_kernel(const float* __restrict__ f0, const float* __restrict__ f1,
             const float* __restrict__ f2, const float* __restrict__ f3,
             const float* __restrict__ boxes, float* __restrict__ out)
{
    __shared__ float2 win[8][3][WS2];                     // 96 KB
    __shared__ float s_hy[14], s_ly[14], s_hx[14], s_lx[14];
    __shared__ int   s_yl[14], s_yh[14], s_xl[14], s_xh[14];

    const int tid = threadIdx.x;
    const int n = blockIdx.x;
    const int b = n >> 8;

    float4 bx = __ldg(reinterpret_cast<const float4*>(boxes) + n);

    // LevelMapper: floor(4 + log2(sqrt(w*h)/224) + 1e-6), clip [2,5], -2
    float s = sqrtf((bx.z - bx.x) * (bx.w - bx.y));
    int lvl = (int)floorf(4.0f + log2f(s * (1.0f / 224.0f)) + 1e-6f);
    lvl = min(max(lvl, 2), 5) - 2;

    int H; float sc; const float* base;
    switch (lvl) {
        case 0:  H = 200; sc = 0.25f;    base = f0; break;
        case 1:  H = 100; sc = 0.125f;   base = f1; break;
        case 2:  H = 50;  sc = 0.0625f;  base = f2; break;
        default: H = 25;  sc = 0.03125f; base = f3; break;
    }
    const int HH = H * H;
    base += (size_t)b * 256 * HH;

    float x1s = bx.x * sc, y1s = bx.y * sc;
    float x2s = bx.z * sc, y2s = bx.w * sc;
    float binw = fmaxf(x2s - x1s, 1.0f) * (1.0f / 7.0f);
    float binh = fmaxf(y2s - y1s, 1.0f) * (1.0f / 7.0f);
    float fH = (float)H;

    // window bounds
    float ymin = y1s + 0.25f * binh, ymax = y1s + 6.75f * binh;
    float xmin = x1s + 0.25f * binw, xmax = x1s + 6.75f * binw;
    int y0  = min((int)fmaxf(ymin, 0.0f), H - 1);
    int x0  = min((int)fmaxf(xmin, 0.0f), H - 1);
    int y1m = min((int)fmaxf(fminf(ymax, fH - 1.0f), 0.0f) + 1, H - 1);
    int x1m = min((int)fmaxf(fminf(xmax, fH - 1.0f), 0.0f) + 1, H - 1);
    int hr  = y1m - y0 + 1;
    int x0d = x0 & ~1;                         // float2-aligned window start
    int wc2 = (x1m >> 1) - (x0d >> 1) + 1;     // float2 per row
    int rs2 = wc2 | 1;                         // odd float2 row stride
    const int rsF = rs2 * 2;                   // float row stride

    // per-sample bilinear params (14 y, 14 x), window-relative indices
    if (tid < 28) {
        bool isY = tid < 14;
        int j = isY ? tid : tid - 14;
        float o = (float)(j >> 1) + 0.25f + 0.5f * (float)(j & 1);
        float v = isY ? (y1s + o * binh) : (x1s + o * binw);
        bool valid = (v > -1.0f) && (v < fH);
        float vc = fmaxf(v, 0.0f);
        int lo = min((int)vc, H - 1);
        int hi = min(lo + 1, H - 1);
        float l = (lo >= H - 1) ? 0.0f : (vc - (float)lo);
        float h = 1.0f - l;
        if (!valid) { l = 0.0f; h = 0.0f; lo = isY ? y0 : x0d; hi = lo; }
        if (isY) { s_yl[j] = lo - y0;  s_yh[j] = hi - y0;  s_ly[j] = l; s_hy[j] = h; }
        else     { s_xl[j] = lo - x0d; s_xh[j] = hi - x0d; s_lx[j] = l; s_hx[j] = h; }
    }
    __syncthreads();                           // only block barrier

    const int warp = tid >> 5, lane = tid & 31;
    const int cbase = blockIdx.y * 64;

    // ---- per-lane register params: binA = lane, binB = 32+lane (lane<17) ----
    int Ar0a, Ar1a, Ar0b, Ar1b, Axl0, Axh0, Axl1, Axh1;
    float Ahy0, Aly0, Ahy1, Aly1, Ahx0, Alx0, Ahx1, Alx1;
    {
        int bin = lane;
        int oy = bin / 7, ox = bin - oy * 7;
        int j0 = oy * 2, j1 = j0 + 1, k0 = ox * 2, k1 = k0 + 1;
        Ar0a = s_yl[j0] * rsF; Ar1a = s_yh[j0] * rsF;
        Ar0b = s_yl[j1] * rsF; Ar1b = s_yh[j1] * rsF;
        Axl0 = s_xl[k0]; Axh0 = s_xh[k0]; Axl1 = s_xl[k1]; Axh1 = s_xh[k1];
        Ahy0 = s_hy[j0]; Aly0 = s_ly[j0]; Ahy1 = s_hy[j1]; Aly1 = s_ly[j1];
        Ahx0 = s_hx[k0]; Alx0 = s_lx[k0]; Ahx1 = s_hx[k1]; Alx1 = s_lx[k1];
    }
    const bool hasB = lane < 17;
    int Br0a = 0, Br1a = 0, Br0b = 0, Br1b = 0, Bxl0 = 0, Bxh0 = 0, Bxl1 = 0, Bxh1 = 0;
    float Bhy0 = 0, Bly0 = 0, Bhy1 = 0, Bly1 = 0, Bhx0 = 0, Blx0 = 0, Bhx1 = 0, Blx1 = 0;
    if (hasB) {
        int bin = 32 + lane;
        int oy = bin / 7, ox = bin - oy * 7;
        int j0 = oy * 2, j1 = j0 + 1, k0 = ox * 2, k1 = k0 + 1;
        Br0a = s_yl[j0] * rsF; Br1a = s_yh[j0] * rsF;
        Br0b = s_yl[j1] * rsF; Br1b = s_yh[j1] * rsF;
        Bxl0 = s_xl[k0]; Bxh0 = s_xh[k0]; Bxl1 = s_xl[k1]; Bxh1 = s_xh[k1];
        Bhy0 = s_hy[j0]; Bly0 = s_ly[j0]; Bhy1 = s_hy[j1]; Bly1 = s_ly[j1];
        Bhx0 = s_hx[k0]; Blx0 = s_lx[k0]; Bhx1 = s_hx[k1]; Blx1 = s_lx[k1];
    }

    const bool fits = (hr * rs2) <= WS2;       // uniform per block
    const bool h25 = (H == 25);
    const int H2 = H >> 1;
    const int xlim = x1m - x0d;

    // staging lane geometry (uniform per warp)
    const int wide = h25 ? (wc2 * 2) : wc2;    // elements per row (f32 / f2)
    int wp2 = 1;
    while (wp2 < wide && wp2 < 32) wp2 <<= 1;
    const int shift = __popc(wp2 - 1);
    const int rpw = 32 >> shift;
    const int lxe = lane & (wp2 - 1);
    const int lr0 = lane >> shift;

    float* outn = out + (size_t)n * 12544;

    if (fits) {
        // ---- warp-private 3-buffer cp.async pipeline over 8 channels ----
        auto stage = [&](int bf, int k) {
            const int cglob = cbase + k * 8 + warp;
            uint32_t wb = (uint32_t)__cvta_generic_to_shared(&win[warp][bf][0]);
            if (!h25) {
                const float2* src = reinterpret_cast<const float2*>(base)
                                  + (size_t)cglob * (HH >> 1) + y0 * H2 + (x0d >> 1);
                for (int cx0 = 0; cx0 < wc2; cx0 += wp2) {
                    int xx = cx0 + lxe;
                    bool inx = xx < wc2;
                    for (int r = lr0; r < hr; r += rpw)
                        cp_async8(wb + (uint32_t)(r * rs2 + xx) * 8u,
                                  src + r * H2 + xx, inx);
                }
            } else {
                const float* src = base + (size_t)cglob * HH + y0 * H + x0d;
                for (int cx0 = 0; cx0 < wide; cx0 += wp2) {
                    int xx = cx0 + lxe;
                    bool inx = xx <= xlim;
                    for (int r = lr0; r < hr; r += rpw)
                        cp_async4(wb + (uint32_t)(r * rsF + xx) * 4u,
                                  src + r * H + xx, inx);
                }
            }
        };

        stage(0, 0); CP_COMMIT();
        stage(1, 1); CP_COMMIT();

        #pragma unroll 1
        for (int k = 0; k < 8; k++) {
            int bf = k % 3;
            if (k + 2 < 8) {
                stage((k + 2) % 3, k + 2);
                CP_COMMIT();
                CP_WAIT(2);
            } else if (k + 1 < 8) {
                CP_WAIT(1);
            } else {
                CP_WAIT(0);
            }
            __syncwarp();

            const float* W = reinterpret_cast<const float*>(win[warp][bf]);
            float accA =
                  Ahy0 * (Ahx0 * W[Ar0a + Axl0] + Alx0 * W[Ar0a + Axh0])
                + Aly0 * (Ahx0 * W[Ar1a + Axl0] + Alx0 * W[Ar1a + Axh0])
                + Ahy0 * (Ahx1 * W[Ar0a + Axl1] + Alx1 * W[Ar0a + Axh1])
                + Aly0 * (Ahx1 * W[Ar1a + Axl1] + Alx1 * W[Ar1a + Axh1])
                + Ahy1 * (Ahx0 * W[Ar0b + Axl0] + Alx0 * W[Ar0b + Axh0])
                + Aly1 * (Ahx0 * W[Ar1b + Axl0] + Alx0 * W[Ar1b + Axh0])
                + Ahy1 * (Ahx1 * W[Ar0b + Axl1] + Alx1 * W[Ar0b + Axh1])
                + Aly1 * (Ahx1 * W[Ar1b + Axl1] + Alx1 * W[Ar1b + Axh1]);
            float accB = 0.0f;
            if (hasB) {
                accB =
                      Bhy0 * (Bhx0 * W[Br0a + Bxl0] + Blx0 * W[Br0a + Bxh0])
                    + Bly0 * (Bhx0 * W[Br1a + Bxl0] + Blx0 * W[Br1a + Bxh0])
                    + Bhy0 * (Bhx1 * W[Br0a + Bxl1] + Blx1 * W[Br0a + Bxh1])
                    + Bly0 * (Bhx1 * W[Br1a + Bxl1] + Blx1 * W[Br1a + Bxh1])
                    + Bhy1 * (Bhx0 * W[Br0b + Bxl0] + Blx0 * W[Br0b + Bxh0])
                    + Bly1 * (Bhx0 * W[Br1b + Bxl0] + Blx0 * W[Br1b + Bxh0])
                    + Bhy1 * (Bhx1 * W[Br0b + Bxl1] + Blx1 * W[Br0b + Bxh1])
                    + Bly1 * (Bhx1 * W[Br1b + Bxl1] + Blx1 * W[Br1b + Bxh1]);
            }
            float* on = outn + (cbase + k * 8 + warp) * 49;
            on[lane] = accA * 0.25f;
            if (hasB) on[32 + lane] = accB * 0.25f;
            __syncwarp();
        }
    } else {
        // ---- rare oversized window: direct global gather (MLP 16) ----
        #pragma unroll 1
        for (int k = 0; k < 8; k++) {
            const int cglob = cbase + k * 8 + warp;
            const float* src = base + (size_t)cglob * HH;
            float acc2[2];
            #pragma unroll
            for (int half = 0; half < 2; half++) {
                int bin = half * 32 + lane;
                bool act = (half == 0) || hasB;
                if (!act) { acc2[half] = 0.0f; continue; }
                int oy = bin / 7, ox = bin - oy * 7;
                float acc = 0.0f;
                #pragma unroll
                for (int sy = 0; sy < 2; sy++) {
                    int j = oy * 2 + sy;
                    float hy = s_hy[j], ly = s_ly[j];
                    int ra = (s_yl[j] + y0) * H, rb = (s_yh[j] + y0) * H;
                    #pragma unroll
                    for (int sx = 0; sx < 2; sx++) {
                        int kk = ox * 2 + sx;
                        float hx = s_hx[kk], lx = s_lx[kk];
                        int xa = s_xl[kk] + x0d, xb = s_xh[kk] + x0d;
                        acc += hy * (hx * __ldg(src + ra + xa) + lx * __ldg(src + ra + xb))
                             + ly * (hx * __ldg(src + rb + xa) + lx * __ldg(src + rb + xb));
                    }
                }
                acc2[half] = acc;
            }
            float* on = outn + cglob * 49;
            on[lane] = acc2[0] * 0.25f;
            if (hasB) on[32 + lane] = acc2[1] * 0.25f;
        }
    }
}

extern "C" void kernel_launch(void* const* d_in, const int* in_sizes, int n_in,
                              void* d_out, int out_size)
{
    const float* f0 = (const float*)d_in[0];
    const float* f1 = (const float*)d_in[1];
    const float* f2 = (const float*)d_in[2];
    const float* f3 = (const float*)d_in[3];
    const float* boxes = (const float*)d_in[4];
    float* out = (float*)d_out;

    msroi_kernel<<<dim3(512, 4), 256>>>(f0, f1, f2, f3, boxes, out);
}